// round 14
// baseline (speedup 1.0000x reference)
#include <cuda_runtime.h>
#include <cstdint>

#define M_NODES   8192
#define K_PAR     8
#define C_CFG     256
#define N_LAYERS  8
#define TPB       512                          // 16 warps
#define NPB       64                           // nodes per block per layer
#define TILE_F    (NPB * C_CFG)                // 16384 floats
#define TILE_B    (TILE_F * 4)                 // 65536 bytes
#define NBUF      2                            // double buffer (128 KB)
#define NBLK      (M_NODES / NPB)              // 128 blocks (1/SM, co-resident)

__device__ unsigned int g_done[N_LAYERS + 1];  // [0]=roots ready .. [8]=all done

__device__ __forceinline__ uint32_t smem_u32(const void* p) {
    uint32_t a;
    asm("{ .reg .u64 t; cvta.to.shared.u64 t, %1; cvt.u32.u64 %0, t; }"
        : "=r"(a) : "l"(p));
    return a;
}

__device__ __forceinline__ float fast_tanh(float x) {
    float r;
    asm("tanh.approx.f32 %0, %1;" : "=f"(r) : "f"(x));
    return r;
}

__device__ __forceinline__ float acc_sigmoid(float x) {
    float t = -1.4426950408889634f * x, e, r;
    asm("ex2.approx.f32 %0, %1;" : "=f"(e) : "f"(t));
    float d = 1.0f + e;
    asm("rcp.approx.f32 %0, %1;" : "=f"(r) : "f"(d));
    return r;
}

__device__ __forceinline__ void mbar_wait(uint32_t mbar_a, uint32_t parity) {
    uint32_t done;
    asm volatile(
        "{\n\t.reg .pred q;\n\t"
        "mbarrier.try_wait.parity.shared.b64 q, [%1], %2;\n\t"
        "selp.b32 %0, 1, 0, q;\n\t}"
        : "=r"(done) : "r"(mbar_a), "r"(parity) : "memory");
    while (!done) {
        asm volatile(
            "{\n\t.reg .pred q;\n\t"
            "mbarrier.try_wait.parity.shared.b64 q, [%1], %2, 1000000;\n\t"
            "selp.b32 %0, 1, 0, q;\n\t}"
            : "=r"(done) : "r"(mbar_a), "r"(parity) : "memory");
    }
}

__device__ __forceinline__ void tma_tile(uint32_t smem_dst, const float* gsrc,
                                         uint32_t mbar_a) {
    asm volatile("mbarrier.arrive.expect_tx.shared.b64 _, [%0], %1;"
                 :: "r"(mbar_a), "r"((uint32_t)TILE_B) : "memory");
    asm volatile(
        "cp.async.bulk.shared::cta.global.mbarrier::complete_tx::bytes "
        "[%0], [%1], %2, [%3];"
        :: "r"(smem_dst), "l"(gsrc), "r"((uint32_t)TILE_B), "r"(mbar_a)
        : "memory");
}

__device__ __forceinline__ void signal_release(unsigned int* ctr) {
    asm volatile("red.release.gpu.global.add.u32 [%0], %1;"
                 :: "l"(ctr), "r"(1u) : "memory");
}

// Every thread spins itself: acquire orders this thread's subsequent loads.
__device__ __forceinline__ void wait_acquire_all(unsigned int* ctr) {
    unsigned v;
    do {
        asm volatile("ld.acquire.gpu.global.u32 %0, [%1];"
                     : "=r"(v) : "l"(ctr) : "memory");
        if (v >= NBLK) break;
        __nanosleep(16);
    } while (true);
}

__global__ void __launch_bounds__(TPB)
persist_kernel(const float* __restrict__ root,
               const float* __restrict__ cpt,      // [L, M, C]
               const int*   __restrict__ parents,  // [L, M, K]
               float*       __restrict__ out)      // [(L+1)*M]
{
    extern __shared__ __align__(16) float buf[];   // 2 * TILE_F floats
    __shared__ __align__(8) uint64_t mbar[NBUF];

    const int tid   = threadIdx.x;
    const int lane  = tid & 31;
    const int wid   = tid >> 5;                    // 0..15
    const int nloc  = wid * 4 + (lane >> 3);       // 0..63: this thread's node
    const int pbase = lane & 24;
    const int nbase = blockIdx.x * NPB;

    const uint32_t mb0 = smem_u32(&mbar[0]);
    const uint32_t mb1 = smem_u32(&mbar[1]);

    if (tid == 0) {
        asm volatile("mbarrier.init.shared.b64 [%0], 1;" :: "r"(mb0) : "memory");
        asm volatile("mbarrier.init.shared.b64 [%0], 1;" :: "r"(mb1) : "memory");
        asm volatile("fence.proxy.async.shared::cta;" ::: "memory");
        tma_tile(smem_u32(buf),          cpt + (size_t)nbase * C_CFG,             mb0);
        tma_tile(smem_u32(buf + TILE_F), cpt + (size_t)(M_NODES + nbase) * C_CFG, mb1);
    }

    // Root marginals for this block's 64 nodes, then release them.
    if (tid < NPB)
        out[nbase + tid] = acc_sigmoid(root[nbase + tid]);
    __syncthreads();   // roots stored + mbarrier init visible
    if (tid == 0)
        signal_release(&g_done[0]);

    // Shadow prep for layer 0: parent index + tile residency (cheap).
    int pidx = parents[(size_t)nbase * K_PAR + tid];
    mbar_wait(mb0, 0);

#pragma unroll 1
    for (int l = 0; l < N_LAYERS; l++) {
        const int    bsel = l & 1;
        const float* tb   = buf + bsel * TILE_F;

        // 1. Wake (all threads; per-thread acquire orders the gather below).
        wait_acquire_all(&g_done[l]);

        // 2. Issue the random gather NOW...
        const float pp = out[(size_t)l * M_NODES + pidx];

        // 3. ...and hide its latency under the tanh burst (independent).
        //    Mapping (validated R2-R13): config c = i*32 + gl*4 + t;
        //    bit b <-> parent (7-b). t bits->parents 7,6 ; gl bits->5,4,3
        //    (shfl_xor); i bits->2,1,0. marginal = 0.5 + 0.5*fold.
        float s[32];
        {
            const float4* row =
                reinterpret_cast<const float4*>(tb + nloc * C_CFG) + (lane & 7);
#pragma unroll
            for (int i = 0; i < 8; i++) {
                float4 v = row[i * 8];
                s[4*i+0] = fast_tanh(0.5f * v.x);
                s[4*i+1] = fast_tanh(0.5f * v.y);
                s[4*i+2] = fast_tanh(0.5f * v.z);
                s[4*i+3] = fast_tanh(0.5f * v.w);
            }
        }

        // 4. Broadcast parent marginals (pp arrived during the tanh burst).
        float p[8];
#pragma unroll
        for (int j = 0; j < 8; j++)
            p[j] = __shfl_sync(0xffffffffu, pp, pbase | j);

        // 5. Fold.
        float r_i[8];
#pragma unroll
        for (int i = 0; i < 8; i++) {
            float t0 = fmaf(p[7], s[4*i+1] - s[4*i+0], s[4*i+0]);
            float t1 = fmaf(p[7], s[4*i+3] - s[4*i+2], s[4*i+2]);
            r_i[i]   = fmaf(p[6], t1 - t0, t0);
        }
        float q0 = fmaf(p[2], r_i[1] - r_i[0], r_i[0]);
        float q1 = fmaf(p[2], r_i[3] - r_i[2], r_i[2]);
        float q2 = fmaf(p[2], r_i[5] - r_i[4], r_i[4]);
        float q3 = fmaf(p[2], r_i[7] - r_i[6], r_i[6]);
        float h0 = fmaf(p[1], q1 - q0, q0);
        float h1 = fmaf(p[1], q3 - q2, q2);
        float r  = fmaf(p[0], h1 - h0, h0);
#pragma unroll
        for (int b = 0; b < 3; b++) {
            int   msk = 1 << b;
            float o   = __shfl_xor_sync(0xffffffffu, r, msk);
            float a0  = (lane & msk) ? o : r;
            float a1  = (lane & msk) ? r : o;
            r = fmaf(p[5 - b], a1 - a0, a0);
        }

        if ((lane & 7) == 0)
            out[(size_t)(l + 1) * M_NODES + nbase + nloc] = fmaf(0.5f, r, 0.5f);

        // 6. All stores done + tile buffer fully read -> signal + refill.
        __syncthreads();
        if (tid == 0) {
            signal_release(&g_done[l + 1]);
            if (l + 2 < N_LAYERS)
                tma_tile(smem_u32(buf + bsel * TILE_F),
                         cpt + ((size_t)(l + 2) * M_NODES + nbase) * C_CFG,
                         bsel ? mb1 : mb0);
        }

        // 7. Shadow prep for layer l+1 (cheap; fits in handoff window).
        if (l + 1 < N_LAYERS) {
            pidx = parents[((size_t)(l + 1) * M_NODES + nbase) * K_PAR + tid];
            mbar_wait((l + 1) & 1 ? mb1 : mb0, ((l + 1) >> 1) & 1);
        }
    }

    // Replay-safe counter reset (ordered after all release signals).
    if (blockIdx.x == 0 && tid == 0) {
        unsigned v;
        do {
            asm volatile("ld.acquire.gpu.global.u32 %0, [%1];"
                         : "=r"(v) : "l"(&g_done[N_LAYERS]) : "memory");
            if (v >= NBLK) break;
            __nanosleep(16);
        } while (true);
#pragma unroll
        for (int i = 0; i <= N_LAYERS; i++)
            g_done[i] = 0;
        __threadfence();
    }
}

extern "C" void kernel_launch(void* const* d_in, const int* in_sizes, int n_in,
                              void* d_out, int out_size) {
    const float* root    = (const float*)d_in[0];  // [M]
    const float* cpt     = (const float*)d_in[1];  // [L, M, C]
    const int*   parents = (const int*)  d_in[2];  // [L, M, K]
    float*       out     = (float*)d_out;          // [(L+1)*M]

    static const int SMEM_DYN = NBUF * TILE_B;     // 128 KB
    cudaFuncSetAttribute(persist_kernel,
                         cudaFuncAttributeMaxDynamicSharedMemorySize, SMEM_DYN);

    persist_kernel<<<NBLK, TPB, SMEM_DYN>>>(root, cpt, parents, out);
}

// round 15
// speedup vs baseline: 1.6591x; 1.6591x over previous
#include <cuda_runtime.h>
#include <cstdint>

#define M_NODES   8192
#define K_PAR     8
#define C_CFG     256
#define N_LAYERS  8
#define TPB       512                          // 16 warps
#define NPB       64                           // nodes per block per layer
#define TILE_F    (NPB * C_CFG)                // 16384 floats
#define TILE_B    (TILE_F * 4)                 // 65536 bytes
#define NBUF      2                            // double buffer (128 KB)
#define NBLK      (M_NODES / NPB)              // 128 blocks (1/SM, co-resident)

__device__ unsigned int g_done[N_LAYERS + 1];  // [0]=roots ready .. [8]=all done

__device__ __forceinline__ uint32_t smem_u32(const void* p) {
    uint32_t a;
    asm("{ .reg .u64 t; cvta.to.shared.u64 t, %1; cvt.u32.u64 %0, t; }"
        : "=r"(a) : "l"(p));
    return a;
}

__device__ __forceinline__ float fast_tanh(float x) {
    float r;
    asm("tanh.approx.f32 %0, %1;" : "=f"(r) : "f"(x));
    return r;
}

__device__ __forceinline__ float acc_sigmoid(float x) {
    float t = -1.4426950408889634f * x, e, r;
    asm("ex2.approx.f32 %0, %1;" : "=f"(e) : "f"(t));
    float d = 1.0f + e;
    asm("rcp.approx.f32 %0, %1;" : "=f"(r) : "f"(d));
    return r;
}

__device__ __forceinline__ void mbar_wait(uint32_t mbar_a, uint32_t parity) {
    uint32_t done;
    asm volatile(
        "{\n\t.reg .pred q;\n\t"
        "mbarrier.try_wait.parity.shared.b64 q, [%1], %2;\n\t"
        "selp.b32 %0, 1, 0, q;\n\t}"
        : "=r"(done) : "r"(mbar_a), "r"(parity) : "memory");
    while (!done) {
        asm volatile(
            "{\n\t.reg .pred q;\n\t"
            "mbarrier.try_wait.parity.shared.b64 q, [%1], %2, 1000000;\n\t"
            "selp.b32 %0, 1, 0, q;\n\t}"
            : "=r"(done) : "r"(mbar_a), "r"(parity) : "memory");
    }
}

__device__ __forceinline__ void tma_tile(uint32_t smem_dst, const float* gsrc,
                                         uint32_t mbar_a) {
    asm volatile("mbarrier.arrive.expect_tx.shared.b64 _, [%0], %1;"
                 :: "r"(mbar_a), "r"((uint32_t)TILE_B) : "memory");
    asm volatile(
        "cp.async.bulk.shared::cta.global.mbarrier::complete_tx::bytes "
        "[%0], [%1], %2, [%3];"
        :: "r"(smem_dst), "l"(gsrc), "r"((uint32_t)TILE_B), "r"(mbar_a)
        : "memory");
}

__device__ __forceinline__ void signal_release(unsigned int* ctr) {
    asm volatile("red.release.gpu.global.add.u32 [%0], %1;"
                 :: "l"(ctr), "r"(1u) : "memory");
}

// tid0-only spin (R13-validated): low L2 traffic, syncthreads broadcasts.
__device__ __forceinline__ void wait_acquire(unsigned int* ctr) {
    unsigned v;
    do {
        asm volatile("ld.acquire.gpu.global.u32 %0, [%1];"
                     : "=r"(v) : "l"(ctr) : "memory");
        if (v >= NBLK) break;
        __nanosleep(32);
    } while (true);
}

__global__ void __launch_bounds__(TPB)
persist_kernel(const float* __restrict__ root,
               const float* __restrict__ cpt,      // [L, M, C]
               const int*   __restrict__ parents,  // [L, M, K]
               float*       __restrict__ out)      // [(L+1)*M]
{
    extern __shared__ __align__(16) float buf[];   // 2 * TILE_F floats
    __shared__ __align__(8) uint64_t mbar[NBUF];

    const int tid   = threadIdx.x;
    const int lane  = tid & 31;
    const int wid   = tid >> 5;                    // 0..15
    const int nloc  = wid * 4 + (lane >> 3);       // 0..63: this thread's node
    const int pbase = lane & 24;
    const int nbase = blockIdx.x * NPB;

    const uint32_t mb0 = smem_u32(&mbar[0]);
    const uint32_t mb1 = smem_u32(&mbar[1]);

    if (tid == 0) {
        asm volatile("mbarrier.init.shared.b64 [%0], 1;" :: "r"(mb0) : "memory");
        asm volatile("mbarrier.init.shared.b64 [%0], 1;" :: "r"(mb1) : "memory");
        asm volatile("fence.proxy.async.shared::cta;" ::: "memory");
        tma_tile(smem_u32(buf),          cpt + (size_t)nbase * C_CFG,             mb0);
        tma_tile(smem_u32(buf + TILE_F), cpt + (size_t)(M_NODES + nbase) * C_CFG, mb1);
    }

    // Root marginals for this block's 64 nodes, then release them.
    if (tid < NPB)
        out[nbase + tid] = acc_sigmoid(root[nbase + tid]);
    __syncthreads();   // roots stored + mbarrier init visible
    if (tid == 0)
        signal_release(&g_done[0]);

    // Shadow prep for layer 0: parent index + tile residency (cheap).
    int pidx = parents[(size_t)nbase * K_PAR + tid];
    mbar_wait(mb0, 0);

#pragma unroll 1
    for (int l = 0; l < N_LAYERS; l++) {
        const int    bsel = l & 1;
        const float* tb   = buf + bsel * TILE_F;

        // 1. Wake: tid0 spins, syncthreads broadcasts (R13-proven).
        if (tid == 0) wait_acquire(&g_done[l]);
        __syncthreads();

        // 2. Issue the random gather immediately...
        const float pp = out[(size_t)l * M_NODES + pidx];

        // 3. ...and hide its latency under the tanh burst (independent).
        //    Mapping (validated R2-R13): config c = i*32 + gl*4 + t;
        //    bit b <-> parent (7-b). t bits->parents 7,6 ; gl bits->5,4,3
        //    (shfl_xor); i bits->2,1,0. marginal = 0.5 + 0.5*fold.
        float s[32];
        {
            const float4* row =
                reinterpret_cast<const float4*>(tb + nloc * C_CFG) + (lane & 7);
#pragma unroll
            for (int i = 0; i < 8; i++) {
                float4 v = row[i * 8];
                s[4*i+0] = fast_tanh(0.5f * v.x);
                s[4*i+1] = fast_tanh(0.5f * v.y);
                s[4*i+2] = fast_tanh(0.5f * v.z);
                s[4*i+3] = fast_tanh(0.5f * v.w);
            }
        }

        // 4. Broadcast parent marginals (pp arrived during the tanh burst).
        float p[8];
#pragma unroll
        for (int j = 0; j < 8; j++)
            p[j] = __shfl_sync(0xffffffffu, pp, pbase | j);

        // 5. Fold.
        float r_i[8];
#pragma unroll
        for (int i = 0; i < 8; i++) {
            float t0 = fmaf(p[7], s[4*i+1] - s[4*i+0], s[4*i+0]);
            float t1 = fmaf(p[7], s[4*i+3] - s[4*i+2], s[4*i+2]);
            r_i[i]   = fmaf(p[6], t1 - t0, t0);
        }
        float q0 = fmaf(p[2], r_i[1] - r_i[0], r_i[0]);
        float q1 = fmaf(p[2], r_i[3] - r_i[2], r_i[2]);
        float q2 = fmaf(p[2], r_i[5] - r_i[4], r_i[4]);
        float q3 = fmaf(p[2], r_i[7] - r_i[6], r_i[6]);
        float h0 = fmaf(p[1], q1 - q0, q0);
        float h1 = fmaf(p[1], q3 - q2, q2);
        float r  = fmaf(p[0], h1 - h0, h0);
#pragma unroll
        for (int b = 0; b < 3; b++) {
            int   msk = 1 << b;
            float o   = __shfl_xor_sync(0xffffffffu, r, msk);
            float a0  = (lane & msk) ? o : r;
            float a1  = (lane & msk) ? r : o;
            r = fmaf(p[5 - b], a1 - a0, a0);
        }

        if ((lane & 7) == 0)
            out[(size_t)(l + 1) * M_NODES + nbase + nloc] = fmaf(0.5f, r, 0.5f);

        // 6. All stores done + tile buffer fully read -> signal + refill.
        __syncthreads();
        if (tid == 0) {
            signal_release(&g_done[l + 1]);
            if (l + 2 < N_LAYERS)
                tma_tile(smem_u32(buf + bsel * TILE_F),
                         cpt + ((size_t)(l + 2) * M_NODES + nbase) * C_CFG,
                         bsel ? mb1 : mb0);
        }

        // 7. Shadow prep for layer l+1 (cheap; fits in handoff window).
        if (l + 1 < N_LAYERS) {
            pidx = parents[((size_t)(l + 1) * M_NODES + nbase) * K_PAR + tid];
            mbar_wait((l + 1) & 1 ? mb1 : mb0, ((l + 1) >> 1) & 1);
        }
    }

    // Replay-safe counter reset (ordered after all release signals).
    if (blockIdx.x == 0 && tid == 0) {
        wait_acquire(&g_done[N_LAYERS]);
#pragma unroll
        for (int i = 0; i <= N_LAYERS; i++)
            g_done[i] = 0;
        __threadfence();
    }
}

extern "C" void kernel_launch(void* const* d_in, const int* in_sizes, int n_in,
                              void* d_out, int out_size) {
    const float* root    = (const float*)d_in[0];  // [M]
    const float* cpt     = (const float*)d_in[1];  // [L, M, C]
    const int*   parents = (const int*)  d_in[2];  // [L, M, K]
    float*       out     = (float*)d_out;          // [(L+1)*M]

    static const int SMEM_DYN = NBUF * TILE_B;     // 128 KB
    cudaFuncSetAttribute(persist_kernel,
                         cudaFuncAttributeMaxDynamicSharedMemorySize, SMEM_DYN);

    persist_kernel<<<NBLK, TPB, SMEM_DYN>>>(root, cpt, parents, out);
}

// round 16
// speedup vs baseline: 1.8250x; 1.1000x over previous
#include <cuda_runtime.h>
#include <cstdint>

#define M_NODES   8192
#define K_PAR     8
#define C_CFG     256
#define N_LAYERS  8
#define TPB       512                          // 16 warps
#define NPB       64                           // nodes per block per layer
#define TILE_F    (NPB * C_CFG)                // 16384 floats
#define TILE_B    (TILE_F * 4)                 // 65536 bytes
#define NBUF      2                            // double buffer (128 KB)
#define NBLK      (M_NODES / NPB)              // 128 blocks (1/SM, co-resident)

__device__ unsigned int g_done[N_LAYERS + 1];  // [0]=roots ready .. [8]=all done

__device__ __forceinline__ uint32_t smem_u32(const void* p) {
    uint32_t a;
    asm("{ .reg .u64 t; cvta.to.shared.u64 t, %1; cvt.u32.u64 %0, t; }"
        : "=r"(a) : "l"(p));
    return a;
}

__device__ __forceinline__ float fast_tanh(float x) {
    float r;
    asm("tanh.approx.f32 %0, %1;" : "=f"(r) : "f"(x));
    return r;
}

__device__ __forceinline__ float acc_sigmoid(float x) {
    float t = -1.4426950408889634f * x, e, r;
    asm("ex2.approx.f32 %0, %1;" : "=f"(e) : "f"(t));
    float d = 1.0f + e;
    asm("rcp.approx.f32 %0, %1;" : "=f"(r) : "f"(d));
    return r;
}

__device__ __forceinline__ void mbar_wait(uint32_t mbar_a, uint32_t parity) {
    uint32_t done;
    asm volatile(
        "{\n\t.reg .pred q;\n\t"
        "mbarrier.try_wait.parity.shared.b64 q, [%1], %2;\n\t"
        "selp.b32 %0, 1, 0, q;\n\t}"
        : "=r"(done) : "r"(mbar_a), "r"(parity) : "memory");
    while (!done) {
        asm volatile(
            "{\n\t.reg .pred q;\n\t"
            "mbarrier.try_wait.parity.shared.b64 q, [%1], %2, 1000000;\n\t"
            "selp.b32 %0, 1, 0, q;\n\t}"
            : "=r"(done) : "r"(mbar_a), "r"(parity) : "memory");
    }
}

__device__ __forceinline__ void tma_tile(uint32_t smem_dst, const float* gsrc,
                                         uint32_t mbar_a) {
    asm volatile("mbarrier.arrive.expect_tx.shared.b64 _, [%0], %1;"
                 :: "r"(mbar_a), "r"((uint32_t)TILE_B) : "memory");
    asm volatile(
        "cp.async.bulk.shared::cta.global.mbarrier::complete_tx::bytes "
        "[%0], [%1], %2, [%3];"
        :: "r"(smem_dst), "l"(gsrc), "r"((uint32_t)TILE_B), "r"(mbar_a)
        : "memory");
}

__device__ __forceinline__ void signal_release(unsigned int* ctr) {
    asm volatile("red.release.gpu.global.add.u32 [%0], %1;"
                 :: "l"(ctr), "r"(1u) : "memory");
}

// tid0-only spin (R13-validated): low L2 traffic, syncthreads broadcasts.
__device__ __forceinline__ void wait_acquire(unsigned int* ctr) {
    unsigned v;
    do {
        asm volatile("ld.acquire.gpu.global.u32 %0, [%1];"
                     : "=r"(v) : "l"(ctr) : "memory");
        if (v >= NBLK) break;
        __nanosleep(32);
    } while (true);
}

// Half tanh pass: iterations [i0, i1) of this thread's node row.
__device__ __forceinline__ void tanh_half(const float* __restrict__ tb,
                                          int nloc, int lane,
                                          int i0, int i1, float* s) {
    const float4* row =
        reinterpret_cast<const float4*>(tb + nloc * C_CFG) + (lane & 7);
#pragma unroll
    for (int i = 0; i < 8; i++) {
        if (i >= i0 && i < i1) {
            float4 v = row[i * 8];
            s[4*i+0] = fast_tanh(0.5f * v.x);
            s[4*i+1] = fast_tanh(0.5f * v.y);
            s[4*i+2] = fast_tanh(0.5f * v.z);
            s[4*i+3] = fast_tanh(0.5f * v.w);
        }
    }
}

__global__ void __launch_bounds__(TPB)
persist_kernel(const float* __restrict__ root,
               const float* __restrict__ cpt,      // [L, M, C]
               const int*   __restrict__ parents,  // [L, M, K]
               float*       __restrict__ out)      // [(L+1)*M]
{
    extern __shared__ __align__(16) float buf[];   // 2 * TILE_F floats
    __shared__ __align__(8) uint64_t mbar[NBUF];

    const int tid   = threadIdx.x;
    const int lane  = tid & 31;
    const int wid   = tid >> 5;                    // 0..15
    const int nloc  = wid * 4 + (lane >> 3);       // 0..63: this thread's node
    const int pbase = lane & 24;
    const int nbase = blockIdx.x * NPB;

    const uint32_t mb0 = smem_u32(&mbar[0]);
    const uint32_t mb1 = smem_u32(&mbar[1]);

    if (tid == 0) {
        asm volatile("mbarrier.init.shared.b64 [%0], 1;" :: "r"(mb0) : "memory");
        asm volatile("mbarrier.init.shared.b64 [%0], 1;" :: "r"(mb1) : "memory");
        asm volatile("fence.proxy.async.shared::cta;" ::: "memory");
        tma_tile(smem_u32(buf),          cpt + (size_t)nbase * C_CFG,             mb0);
        tma_tile(smem_u32(buf + TILE_F), cpt + (size_t)(M_NODES + nbase) * C_CFG, mb1);
    }

    // Root marginals for this block's 64 nodes, then release them.
    if (tid < NPB)
        out[nbase + tid] = acc_sigmoid(root[nbase + tid]);
    __syncthreads();   // roots stored + mbarrier init visible
    if (tid == 0)
        signal_release(&g_done[0]);

    // Shadow prep for layer 0: pidx + tile residency + first half tanh.
    int pidx = parents[(size_t)nbase * K_PAR + tid];
    float s[32];
    mbar_wait(mb0, 0);
    tanh_half(buf, nloc, lane, 0, 4, s);

#pragma unroll 1
    for (int l = 0; l < N_LAYERS; l++) {
        const int    bsel = l & 1;
        const float* tb   = buf + bsel * TILE_F;

        // 1. Wake: tid0 spins, syncthreads broadcasts (R13-proven).
        if (tid == 0) wait_acquire(&g_done[l]);
        __syncthreads();

        // 2. Issue the random gather immediately...
        const float pp = out[(size_t)l * M_NODES + pidx];

        // 3. ...hide it under the SECOND half of the tanh burst.
        //    Mapping (validated R2-R15): config c = i*32 + gl*4 + t;
        //    bit b <-> parent (7-b). t bits->parents 7,6 ; gl bits->5,4,3
        //    (shfl_xor); i bits->2,1,0. marginal = 0.5 + 0.5*fold.
        tanh_half(tb, nloc, lane, 4, 8, s);

        // 4. Broadcast parent marginals (pp arrived during the tanh half).
        float p[8];
#pragma unroll
        for (int j = 0; j < 8; j++)
            p[j] = __shfl_sync(0xffffffffu, pp, pbase | j);

        // 5. Fold.
        float r_i[8];
#pragma unroll
        for (int i = 0; i < 8; i++) {
            float t0 = fmaf(p[7], s[4*i+1] - s[4*i+0], s[4*i+0]);
            float t1 = fmaf(p[7], s[4*i+3] - s[4*i+2], s[4*i+2]);
            r_i[i]   = fmaf(p[6], t1 - t0, t0);
        }
        float q0 = fmaf(p[2], r_i[1] - r_i[0], r_i[0]);
        float q1 = fmaf(p[2], r_i[3] - r_i[2], r_i[2]);
        float q2 = fmaf(p[2], r_i[5] - r_i[4], r_i[4]);
        float q3 = fmaf(p[2], r_i[7] - r_i[6], r_i[6]);
        float h0 = fmaf(p[1], q1 - q0, q0);
        float h1 = fmaf(p[1], q3 - q2, q2);
        float r  = fmaf(p[0], h1 - h0, h0);
#pragma unroll
        for (int b = 0; b < 3; b++) {
            int   msk = 1 << b;
            float o   = __shfl_xor_sync(0xffffffffu, r, msk);
            float a0  = (lane & msk) ? o : r;
            float a1  = (lane & msk) ? r : o;
            r = fmaf(p[5 - b], a1 - a0, a0);
        }

        if ((lane & 7) == 0)
            out[(size_t)(l + 1) * M_NODES + nbase + nloc] = fmaf(0.5f, r, 0.5f);

        // 6. All stores done + tile buffer fully read -> signal + refill.
        __syncthreads();
        if (tid == 0) {
            signal_release(&g_done[l + 1]);
            if (l + 2 < N_LAYERS)
                tma_tile(smem_u32(buf + bsel * TILE_F),
                         cpt + ((size_t)(l + 2) * M_NODES + nbase) * C_CFG,
                         bsel ? mb1 : mb0);
        }

        // 7. Shadow prep for layer l+1: pidx + residency + FIRST half tanh.
        if (l + 1 < N_LAYERS) {
            pidx = parents[((size_t)(l + 1) * M_NODES + nbase) * K_PAR + tid];
            const int nb = (l + 1) & 1;
            mbar_wait(nb ? mb1 : mb0, ((l + 1) >> 1) & 1);
            tanh_half(buf + nb * TILE_F, nloc, lane, 0, 4, s);
        }
    }

    // Replay-safe counter reset (ordered after all release signals).
    if (blockIdx.x == 0 && tid == 0) {
        wait_acquire(&g_done[N_LAYERS]);
#pragma unroll
        for (int i = 0; i <= N_LAYERS; i++)
            g_done[i] = 0;
        __threadfence();
    }
}

extern "C" void kernel_launch(void* const* d_in, const int* in_sizes, int n_in,
                              void* d_out, int out_size) {
    const float* root    = (const float*)d_in[0];  // [M]
    const float* cpt     = (const float*)d_in[1];  // [L, M, C]
    const int*   parents = (const int*)  d_in[2];  // [L, M, K]
    float*       out     = (float*)d_out;          // [(L+1)*M]

    static const int SMEM_DYN = NBUF * TILE_B;     // 128 KB
    cudaFuncSetAttribute(persist_kernel,
                         cudaFuncAttributeMaxDynamicSharedMemorySize, SMEM_DYN);

    persist_kernel<<<NBLK, TPB, SMEM_DYN>>>(root, cpt, parents, out);
}